// round 7
// baseline (speedup 1.0000x reference)
#include <cuda_runtime.h>
#include <cuda_bf16.h>
#include <cstdint>

#define NC 256
#define KK 16
#define DD 256
#define NN 4096
#define MARGINF 1.0f
#define EPSF 1e-6f

#define TI 128
#define TJ 128
#define KCB 128          // bytes of k per chunk (128 int8)
#define NCHUNK 2         // K = 256 int8
#define NTI (NN / TI)    // 32
#define NTJ (NN / TJ)    // 32
#define NTILES (NTI * (NTI + 1) / 2)   // 528

#define QSCALE 26.0f
#define INV_S2 (1.0f / (QSCALE * QSCALE))

#define STAGE_BYTES (TI*128 + TJ*128)   // 32 KB
#define SQ_OFF      (2 * STAGE_BYTES)   // 64 KB
#define DYN_SMEM    (SQ_OFF + 1024)

__device__ int8_t g_panel[(size_t)NN * 256];
__device__ float g_sq[NN];
__device__ float g_cand_v[NN * NTJ];
__device__ int   g_cand_j[NN * NTJ];
__device__ int   g_pos_idx[NN];
__device__ unsigned long long g_sum_fix;
__device__ unsigned int g_done;

#define FIX_SCALE 17592186044416.0   // 2^44

#define LDSM4(r, a) \
    asm volatile("ldmatrix.sync.aligned.m8n8.x4.shared.b16 {%0,%1,%2,%3}, [%4];" \
        : "=r"((r)[0]), "=r"((r)[1]), "=r"((r)[2]), "=r"((r)[3]) : "r"(a))

#define IMMA16832(c, a, b) \
    asm volatile("mma.sync.aligned.m16n8k32.row.col.s32.s8.s8.s32 " \
        "{%0,%1,%2,%3}, {%4,%5,%6,%7}, {%8,%9}, {%0,%1,%2,%3};" \
        : "+r"((c)[0]), "+r"((c)[1]), "+r"((c)[2]), "+r"((c)[3]) \
        : "r"((a)[0]), "r"((a)[1]), "r"((a)[2]), "r"((a)[3]), \
          "r"((b)[0]), "r"((b)[1]))

__device__ __forceinline__ void cp16(uint32_t dst, const void* src) {
    asm volatile("cp.async.cg.shared.global [%0], [%1], 16;" :: "r"(dst), "l"(src));
}
#define CP_COMMIT() asm volatile("cp.async.commit_group;")
#define CP_WAIT(n)  asm volatile("cp.async.wait_group %0;" :: "n"(n))

// ---------------- prep: fp32 -> int8 panel + sq + zero accumulators ----------------
__global__ __launch_bounds__(256) void prep_kernel(const float* __restrict__ emb) {
    if (blockIdx.x == 0 && threadIdx.x == 0) { g_sum_fix = 0ull; g_done = 0u; }

    const int wid  = threadIdx.x >> 5;
    const int lane = threadIdx.x & 31;

    #pragma unroll
    for (int rr = 0; rr < 2; rr++) {
        const int row = blockIdx.x * 16 + wid * 2 + rr;

        const float4* src = (const float4*)(emb + (size_t)row * DD);
        float4 a = __ldg(&src[lane * 2]);
        float4 b = __ldg(&src[lane * 2 + 1]);
        float x[8] = {a.x, a.y, a.z, a.w, b.x, b.y, b.z, b.w};

        int8_t q[8];
        float s = 0.f;
        #pragma unroll
        for (int t = 0; t < 8; t++) {
            int v = __float2int_rn(x[t] * QSCALE);
            v = max(-127, min(127, v));
            q[t] = (int8_t)v;
            s += x[t] * x[t];
        }
        *(uint2*)(g_panel + (size_t)row * 256 + lane * 8) = *(const uint2*)q;

        #pragma unroll
        for (int off = 16; off; off >>= 1)
            s += __shfl_xor_sync(0xffffffffu, s, off);
        if (lane == 0) g_sq[row] = s;
    }
}

// ---------------- triangular int8 GEMM + two-sided epilogue ----------------
__global__ __launch_bounds__(256, 2)
void gemm_kernel() {
    extern __shared__ char dsm[];
    const int tid = threadIdx.x;

    // decode blockIdx.x -> (ti, tj) with tj >= ti
    int rem = blockIdx.x, ti = 0;
    while (rem >= NTI - ti) { rem -= NTI - ti; ti++; }
    const int tj = ti + rem;

    const int i0 = ti * TI;
    const int j0 = tj * TJ;
    const int wid = tid >> 5, lane = tid & 31;
    const int wm  = wid >> 2, wn = wid & 3;   // 2 x 4 warp grid
    const bool diag = (ti == tj);

    const uint32_t sbase = (uint32_t)__cvta_generic_to_shared(dsm);
    float* s_sqi = (float*)(dsm + SQ_OFF);
    float* s_sqj = (float*)(dsm + SQ_OFF + 512);

    if (tid < 128) s_sqi[tid] = g_sq[i0 + tid];
    else           s_sqj[tid - 128] = g_sq[j0 + tid - 128];

    const char* gp = (const char*)g_panel;

    auto load_stage = [&](int kc, int s) {
        const uint32_t aBase = sbase + s * STAGE_BYTES;
        const uint32_t bBase = aBase + TI * 128;
        const int koff = kc * KCB;
        #pragma unroll
        for (int it = 0; it < 4; it++) {
            const int idx = tid + 256 * it;
            const int row = idx >> 3, seg = idx & 7;
            const int off = row * 128 + seg * 16;
            cp16(aBase + (off ^ ((off >> 3) & 0x70)),
                 gp + (size_t)(i0 + row) * 256 + koff + seg * 16);
        }
        #pragma unroll
        for (int it = 0; it < 4; it++) {
            const int idx = tid + 256 * it;
            const int row = idx >> 3, seg = idx & 7;
            const int off = row * 128 + seg * 16;
            cp16(bBase + (off ^ ((off >> 3) & 0x70)),
                 gp + (size_t)(j0 + row) * 256 + koff + seg * 16);
        }
        CP_COMMIT();
    };

    load_stage(0, 0);
    load_stage(1, 1);

    int acc[4][4][4];
    #pragma unroll
    for (int a = 0; a < 4; a++)
        #pragma unroll
        for (int b = 0; b < 4; b++)
            #pragma unroll
            for (int c = 0; c < 4; c++) acc[a][b][c] = 0;

    #pragma unroll
    for (int kc = 0; kc < NCHUNK; kc++) {
        if (kc == 0) { CP_WAIT(1); }
        else         { CP_WAIT(0); }
        __syncthreads();

        const uint32_t aBase = sbase + kc * STAGE_BYTES;
        const uint32_t bBase = aBase + TI * 128;

        #pragma unroll
        for (int ks = 0; ks < 4; ks++) {
            uint32_t afr[4][4];
            #pragma unroll
            for (int fm = 0; fm < 4; fm++) {
                const int row = wm * 64 + fm * 16 + (lane & 15);
                const int ch  = (ks * 2 + (lane >> 4)) ^ (row & 7);
                LDSM4(afr[fm], aBase + row * 128 + ch * 16);
            }
            uint32_t bfr[2][4];
            #pragma unroll
            for (int g = 0; g < 2; g++) {
                const int row = wn * 32 + g * 16 + (lane & 7) + ((lane >> 4) & 1) * 8;
                const int ch  = (ks * 2 + ((lane >> 3) & 1)) ^ (row & 7);
                LDSM4(bfr[g], bBase + row * 128 + ch * 16);
            }
            #pragma unroll
            for (int fm = 0; fm < 4; fm++)
                #pragma unroll
                for (int fn = 0; fn < 4; fn++)
                    IMMA16832(acc[fm][fn], afr[fm], &bfr[fn >> 1][(fn & 1) * 2]);
        }
        if (kc == 0) __syncthreads();
    }
    __syncthreads();   // all warps done reading smem before epilogue reuse

    // ---- epilogue: row-side (all tiles) + col-side (off-diag) ----
    float* r_nv = (float*)dsm;               // [128][4]
    int*   r_nj = (int*)(dsm + 2048);
    float* r_pv = (float*)(dsm + 4096);
    int*   r_pj = (int*)(dsm + 6144);
    float* c_nv = (float*)(dsm + 8192);      // [128][2]
    int*   c_nj = (int*)(dsm + 9216);

    #pragma unroll
    for (int fm = 0; fm < 4; fm++) {
        #pragma unroll
        for (int h = 0; h < 2; h++) {
            const int rl = wm * 64 + fm * 16 + h * 8 + (lane >> 2);
            const int i  = i0 + rl;
            const int ci = i >> 4;
            const float sqi = s_sqi[rl];

            float bnv = 3.0e38f;  int bnj = 0x7fffffff;
            float bpv = -3.0e38f; int bpj = 0;

            #pragma unroll
            for (int fn = 0; fn < 4; fn++) {
                #pragma unroll
                for (int e = 0; e < 2; e++) {
                    const int cl = wn * 32 + fn * 8 + (lane & 3) * 2 + e;
                    const int j  = j0 + cl;
                    const float dot = (float)acc[fm][fn][h * 2 + e] * INV_S2;
                    const float d2 = sqi + s_sqj[cl] - 2.f * dot;
                    if (diag && ((j >> 4) == ci)) {
                        if (d2 > bpv) { bpv = d2; bpj = j; }
                    } else {
                        if (d2 < bnv) { bnv = d2; bnj = j; }
                    }
                }
            }
            #pragma unroll
            for (int m = 1; m <= 2; m <<= 1) {
                float ov; int oj;
                ov = __shfl_xor_sync(0xffffffffu, bnv, m);
                oj = __shfl_xor_sync(0xffffffffu, bnj, m);
                if (ov < bnv || (ov == bnv && oj < bnj)) { bnv = ov; bnj = oj; }
                ov = __shfl_xor_sync(0xffffffffu, bpv, m);
                oj = __shfl_xor_sync(0xffffffffu, bpj, m);
                if (ov > bpv || (ov == bpv && oj < bpj)) { bpv = ov; bpj = oj; }
            }
            if ((lane & 3) == 0) {
                r_nv[rl * 4 + wn] = bnv; r_nj[rl * 4 + wn] = bnj;
                if (diag) { r_pv[rl * 4 + wn] = bpv; r_pj[rl * 4 + wn] = bpj; }
            }
        }
    }

    if (!diag) {
        #pragma unroll
        for (int fn = 0; fn < 4; fn++) {
            #pragma unroll
            for (int e = 0; e < 2; e++) {
                const int cl = wn * 32 + fn * 8 + (lane & 3) * 2 + e;
                const float sqj = s_sqj[cl];
                float bv = 3.0e38f; int bi = 0x7fffffff;
                #pragma unroll
                for (int fm = 0; fm < 4; fm++) {
                    #pragma unroll
                    for (int h = 0; h < 2; h++) {
                        const int rl = wm * 64 + fm * 16 + h * 8 + (lane >> 2);
                        const float dot = (float)acc[fm][fn][h * 2 + e] * INV_S2;
                        const float d2 = s_sqi[rl] + sqj - 2.f * dot;
                        if (d2 < bv) { bv = d2; bi = i0 + rl; }
                    }
                }
                #pragma unroll
                for (int m = 4; m <= 16; m <<= 1) {
                    const float ov = __shfl_xor_sync(0xffffffffu, bv, m);
                    const int   oi = __shfl_xor_sync(0xffffffffu, bi, m);
                    if (ov < bv || (ov == bv && oi < bi)) { bv = ov; bi = oi; }
                }
                if ((lane >> 2) == 0) { c_nv[cl * 2 + wm] = bv; c_nj[cl * 2 + wm] = bi; }
            }
        }
    }
    __syncthreads();

    if (tid < 128) {
        float v = r_nv[tid * 4]; int bj = r_nj[tid * 4];
        #pragma unroll
        for (int w = 1; w < 4; w++) {
            const float ov = r_nv[tid * 4 + w];
            const int   oj = r_nj[tid * 4 + w];
            if (ov < v || (ov == v && oj < bj)) { v = ov; bj = oj; }
        }
        g_cand_v[(size_t)(i0 + tid) * NTJ + tj] = v;
        g_cand_j[(size_t)(i0 + tid) * NTJ + tj] = bj;

        if (diag) {
            float pv = r_pv[tid * 4]; int pj = r_pj[tid * 4];
            #pragma unroll
            for (int w = 1; w < 4; w++) {
                const float ov = r_pv[tid * 4 + w];
                const int   oj = r_pj[tid * 4 + w];
                if (ov > pv || (ov == pv && oj < pj)) { pv = ov; pj = oj; }
            }
            g_pos_idx[i0 + tid] = pj;
        }
    } else if (!diag) {
        const int c = tid - 128;
        float v = c_nv[c * 2]; int bi = c_nj[c * 2];
        const float ov = c_nv[c * 2 + 1];
        const int   oi = c_nj[c * 2 + 1];
        if (ov < v || (ov == v && oi < bi)) { v = ov; bi = oi; }
        g_cand_v[(size_t)(j0 + c) * NTJ + ti] = v;
        g_cand_j[(size_t)(j0 + c) * NTJ + ti] = bi;
    }
}

// ---------------- fused finalize: candidates -> exact loss -> deterministic mean ----------------
#define LB 256
__global__ __launch_bounds__(256) void loss_kernel(const float* __restrict__ emb,
                                                   float* __restrict__ out) {
    const int wid = threadIdx.x >> 5, lane = threadIdx.x & 31;
    __shared__ float warp_sum[8];

    float lsum = 0.f;
    #pragma unroll 1
    for (int r = 0; r < NN / (LB * 8); r++) {            // 2 rows per warp
        const int i = blockIdx.x * (NN / LB) + wid * (NN / (LB * 8)) + r;

        float v = g_cand_v[(size_t)i * NTJ + lane];
        int  bj = g_cand_j[(size_t)i * NTJ + lane];
        #pragma unroll
        for (int off = 16; off; off >>= 1) {
            const float ov = __shfl_xor_sync(0xffffffffu, v,  off);
            const int   oi = __shfl_xor_sync(0xffffffffu, bj, off);
            if (ov < v || (ov == v && oi < bj)) { v = ov; bj = oi; }
        }
        const int n = bj;
        const int p = g_pos_idx[i];

        const float4* ei = (const float4*)(emb + (size_t)i * DD);
        const float4* ep = (const float4*)(emb + (size_t)p * DD);
        const float4* en = (const float4*)(emb + (size_t)n * DD);

        float sp = 0.f, sn = 0.f;
        #pragma unroll
        for (int t = 0; t < 2; t++) {
            const int q = lane + 32 * t;
            float4 a = __ldg(&ei[q]);
            float4 b = __ldg(&ep[q]);
            float4 d = __ldg(&en[q]);
            float x;
            x = a.x - b.x + EPSF; sp += x * x;
            x = a.y - b.y + EPSF; sp += x * x;
            x = a.z - b.z + EPSF; sp += x * x;
            x = a.w - b.w + EPSF; sp += x * x;
            x = a.x - d.x + EPSF; sn += x * x;
            x = a.y - d.y + EPSF; sn += x * x;
            x = a.z - d.z + EPSF; sn += x * x;
            x = a.w - d.w + EPSF; sn += x * x;
        }
        #pragma unroll
        for (int off = 16; off; off >>= 1) {
            sp += __shfl_xor_sync(0xffffffffu, sp, off);
            sn += __shfl_xor_sync(0xffffffffu, sn, off);
        }
        if (lane == 0)
            lsum += fmaxf(sqrtf(sp) - sqrtf(sn) + MARGINF, 0.f);
    }
    if (lane == 0) warp_sum[wid] = lsum;
    __syncthreads();

    if (threadIdx.x == 0) {
        double s = 0.0;
        #pragma unroll
        for (int w = 0; w < 8; w++) s += (double)warp_sum[w];
        const unsigned long long fx = (unsigned long long)(s * FIX_SCALE + 0.5);
        atomicAdd(&g_sum_fix, fx);
        __threadfence();
        const unsigned done = atomicAdd(&g_done, 1u);
        if (done == LB - 1) {
            const unsigned long long tot = atomicAdd(&g_sum_fix, 0ull);
            out[0] = (float)((double)tot / FIX_SCALE / (double)NN);
        }
    }
}

extern "C" void kernel_launch(void* const* d_in, const int* in_sizes, int n_in,
                              void* d_out, int out_size) {
    const float* emb = (const float*)d_in[0];
    float* out = (float*)d_out;

    static bool attr_set = false;
    if (!attr_set) {
        cudaFuncSetAttribute(gemm_kernel, cudaFuncAttributeMaxDynamicSharedMemorySize, DYN_SMEM);
        attr_set = true;
    }

    prep_kernel<<<NN / 16, 256>>>(emb);
    gemm_kernel<<<NTILES, 256, DYN_SMEM>>>();
    loss_kernel<<<LB, 256>>>(emb, out);
}

// round 8
// speedup vs baseline: 1.2807x; 1.2807x over previous
#include <cuda_runtime.h>
#include <cuda_bf16.h>
#include <cstdint>

#define NC 256
#define KK 16
#define DD 256
#define NN 4096
#define MARGINF 1.0f
#define EPSF 1e-6f

#define TI 128
#define TJ 128
#define KC 64            // bf16 per k-chunk (128B rows)
#define NCHUNK 4         // K = 256 (hi-only)
#define NTI (NN / TI)    // 32
#define NTJ (NN / TJ)    // 32
#define NTILES (NTI * (NTI + 1) / 2)   // 528

#define STAGE_BYTES (TI*128 + TJ*128)   // 32 KB
#define SQ_OFF      (3 * STAGE_BYTES)   // 96 KB
#define DYN_SMEM    (SQ_OFF + 1024)

__device__ __nv_bfloat16 g_panel[(size_t)NN * 256];   // hi only
__device__ float g_sq[NN];
__device__ float g_cand_v[NN * NTJ];
__device__ int   g_cand_j[NN * NTJ];
__device__ int   g_pos_idx[NN];
__device__ unsigned long long g_sum_fix;
__device__ unsigned int g_done;

#define FIX_SCALE 17592186044416.0   // 2^44

#define LDSM4(r, a) \
    asm volatile("ldmatrix.sync.aligned.m8n8.x4.shared.b16 {%0,%1,%2,%3}, [%4];" \
        : "=r"((r)[0]), "=r"((r)[1]), "=r"((r)[2]), "=r"((r)[3]) : "r"(a))

#define MMA16816(c, a, b) \
    asm volatile("mma.sync.aligned.m16n8k16.row.col.f32.bf16.bf16.f32 " \
        "{%0,%1,%2,%3}, {%4,%5,%6,%7}, {%8,%9}, {%0,%1,%2,%3};" \
        : "+f"((c)[0]), "+f"((c)[1]), "+f"((c)[2]), "+f"((c)[3]) \
        : "r"((a)[0]), "r"((a)[1]), "r"((a)[2]), "r"((a)[3]), \
          "r"((b)[0]), "r"((b)[1]))

__device__ __forceinline__ void cp16(uint32_t dst, const void* src) {
    asm volatile("cp.async.cg.shared.global [%0], [%1], 16;" :: "r"(dst), "l"(src));
}
#define CP_COMMIT() asm volatile("cp.async.commit_group;")
#define CP_WAIT(n)  asm volatile("cp.async.wait_group %0;" :: "n"(n))

// ---------------- prep: fp32 -> bf16 hi panel + sq + zero accumulators ----------------
__global__ __launch_bounds__(256) void prep_kernel(const float* __restrict__ emb) {
    if (blockIdx.x == 0 && threadIdx.x == 0) { g_sum_fix = 0ull; g_done = 0u; }

    const int row  = blockIdx.x * 8 + (threadIdx.x >> 5);
    const int lane = threadIdx.x & 31;

    const float4* src = (const float4*)(emb + (size_t)row * DD);
    float4 a = __ldg(&src[lane * 2]);
    float4 b = __ldg(&src[lane * 2 + 1]);
    float x[8] = {a.x, a.y, a.z, a.w, b.x, b.y, b.z, b.w};

    alignas(16) __nv_bfloat16 hi[8];
    float s = 0.f;
    #pragma unroll
    for (int t = 0; t < 8; t++) {
        hi[t] = __float2bfloat16(x[t]);
        s += x[t] * x[t];
    }
    *(uint4*)(g_panel + (size_t)row * 256 + lane * 8) = *(const uint4*)hi;

    #pragma unroll
    for (int off = 16; off; off >>= 1)
        s += __shfl_xor_sync(0xffffffffu, s, off);
    if (lane == 0) g_sq[row] = s;
}

// ---------------- triangular GEMM (HMMA, cp.async pipeline) + two-sided epilogue ----------------
__global__ __launch_bounds__(256, 2)
void gemm_kernel() {
    extern __shared__ char dsm[];
    const int tid = threadIdx.x;

    // decode blockIdx.x -> (ti, tj) with tj >= ti
    int rem = blockIdx.x, ti = 0;
    while (rem >= NTI - ti) { rem -= NTI - ti; ti++; }
    const int tj = ti + rem;

    const int i0 = ti * TI;
    const int j0 = tj * TJ;
    const int wid = tid >> 5, lane = tid & 31;
    const int wm  = wid >> 2, wn = wid & 3;   // 2 x 4 warp grid
    const bool diag = (ti == tj);

    const uint32_t sbase = (uint32_t)__cvta_generic_to_shared(dsm);
    float* s_sqi = (float*)(dsm + SQ_OFF);
    float* s_sqj = (float*)(dsm + SQ_OFF + 512);

    const char* gp = (const char*)g_panel;

    auto load_stage = [&](int kc, int s) {
        const uint32_t aBase = sbase + s * STAGE_BYTES;
        const uint32_t bBase = aBase + TI * 128;
        const int koff = kc * KC;
        #pragma unroll
        for (int it = 0; it < 4; it++) {
            const int idx = tid + 256 * it;
            const int row = idx >> 3, seg = idx & 7;
            const int off = row * 128 + seg * 16;
            cp16(aBase + (off ^ ((off >> 3) & 0x70)),
                 gp + ((size_t)(i0 + row) * 256 + koff + seg * 8) * 2);
        }
        #pragma unroll
        for (int it = 0; it < 4; it++) {
            const int idx = tid + 256 * it;
            const int row = idx >> 3, seg = idx & 7;
            const int off = row * 128 + seg * 16;
            cp16(bBase + (off ^ ((off >> 3) & 0x70)),
                 gp + ((size_t)(j0 + row) * 256 + koff + seg * 8) * 2);
        }
        CP_COMMIT();
    };

    // fill the pipeline FIRST, then do the (blocking) sq gathers
    load_stage(0, 0);
    load_stage(1, 1);

    if (tid < 128) s_sqi[tid] = g_sq[i0 + tid];
    else           s_sqj[tid - 128] = g_sq[j0 + tid - 128];

    float acc[4][4][4];
    #pragma unroll
    for (int a = 0; a < 4; a++)
        #pragma unroll
        for (int b = 0; b < 4; b++)
            #pragma unroll
            for (int c = 0; c < 4; c++) acc[a][b][c] = 0.f;

    for (int kc = 0; kc < NCHUNK; kc++) {
        if (kc + 2 < NCHUNK) load_stage(kc + 2, (kc + 2) % 3);

        if (kc + 2 < NCHUNK)      { CP_WAIT(2); }
        else if (kc + 1 < NCHUNK) { CP_WAIT(1); }
        else                      { CP_WAIT(0); }
        __syncthreads();

        const uint32_t aBase = sbase + (kc % 3) * STAGE_BYTES;
        const uint32_t bBase = aBase + TI * 128;

        #pragma unroll
        for (int ks = 0; ks < 4; ks++) {
            uint32_t afr[4][4];
            #pragma unroll
            for (int fm = 0; fm < 4; fm++) {
                const int row = wm * 64 + fm * 16 + (lane & 15);
                const int ch  = (ks * 2 + (lane >> 4)) ^ (row & 7);
                LDSM4(afr[fm], aBase + row * 128 + ch * 16);
            }
            uint32_t bfr[2][4];
            #pragma unroll
            for (int g = 0; g < 2; g++) {
                const int row = wn * 32 + g * 16 + (lane & 7) + ((lane >> 4) & 1) * 8;
                const int ch  = (ks * 2 + ((lane >> 3) & 1)) ^ (row & 7);
                LDSM4(bfr[g], bBase + row * 128 + ch * 16);
            }
            #pragma unroll
            for (int fm = 0; fm < 4; fm++)
                #pragma unroll
                for (int fn = 0; fn < 4; fn++)
                    MMA16816(acc[fm][fn], afr[fm], &bfr[fn >> 1][(fn & 1) * 2]);
        }
        __syncthreads();
    }

    // ---- epilogue: row-side (all tiles) + col-side (off-diag) ----
    float* r_nv = (float*)dsm;               // [128][4]
    int*   r_nj = (int*)(dsm + 2048);
    float* r_pv = (float*)(dsm + 4096);
    int*   r_pj = (int*)(dsm + 6144);
    float* c_nv = (float*)(dsm + 8192);      // [128][2]
    int*   c_nj = (int*)(dsm + 9216);

    #pragma unroll
    for (int fm = 0; fm < 4; fm++) {
        #pragma unroll
        for (int h = 0; h < 2; h++) {
            const int rl = wm * 64 + fm * 16 + h * 8 + (lane >> 2);
            const int i  = i0 + rl;
            const int ci = i >> 4;
            const float sqi = s_sqi[rl];

            float bnv = 3.0e38f;  int bnj = 0x7fffffff;
            float bpv = -3.0e38f; int bpj = 0;

            #pragma unroll
            for (int fn = 0; fn < 4; fn++) {
                #pragma unroll
                for (int e = 0; e < 2; e++) {
                    const int cl = wn * 32 + fn * 8 + (lane & 3) * 2 + e;
                    const int j  = j0 + cl;
                    const float d2 = sqi + s_sqj[cl] - 2.f * acc[fm][fn][h * 2 + e];
                    if (diag && ((j >> 4) == ci)) {
                        if (d2 > bpv) { bpv = d2; bpj = j; }
                    } else {
                        if (d2 < bnv) { bnv = d2; bnj = j; }
                    }
                }
            }
            #pragma unroll
            for (int m = 1; m <= 2; m <<= 1) {
                float ov; int oj;
                ov = __shfl_xor_sync(0xffffffffu, bnv, m);
                oj = __shfl_xor_sync(0xffffffffu, bnj, m);
                if (ov < bnv || (ov == bnv && oj < bnj)) { bnv = ov; bnj = oj; }
                ov = __shfl_xor_sync(0xffffffffu, bpv, m);
                oj = __shfl_xor_sync(0xffffffffu, bpj, m);
                if (ov > bpv || (ov == bpv && oj < bpj)) { bpv = ov; bpj = oj; }
            }
            if ((lane & 3) == 0) {
                r_nv[rl * 4 + wn] = bnv; r_nj[rl * 4 + wn] = bnj;
                if (diag) { r_pv[rl * 4 + wn] = bpv; r_pj[rl * 4 + wn] = bpj; }
            }
        }
    }

    if (!diag) {
        #pragma unroll
        for (int fn = 0; fn < 4; fn++) {
            #pragma unroll
            for (int e = 0; e < 2; e++) {
                const int cl = wn * 32 + fn * 8 + (lane & 3) * 2 + e;
                const float sqj = s_sqj[cl];
                float bv = 3.0e38f; int bi = 0x7fffffff;
                #pragma unroll
                for (int fm = 0; fm < 4; fm++) {
                    #pragma unroll
                    for (int h = 0; h < 2; h++) {
                        const int rl = wm * 64 + fm * 16 + h * 8 + (lane >> 2);
                        const float d2 = s_sqi[rl] + sqj - 2.f * acc[fm][fn][h * 2 + e];
                        if (d2 < bv) { bv = d2; bi = i0 + rl; }
                    }
                }
                #pragma unroll
                for (int m = 4; m <= 16; m <<= 1) {
                    const float ov = __shfl_xor_sync(0xffffffffu, bv, m);
                    const int   oi = __shfl_xor_sync(0xffffffffu, bi, m);
                    if (ov < bv || (ov == bv && oi < bi)) { bv = ov; bi = oi; }
                }
                if ((lane >> 2) == 0) { c_nv[cl * 2 + wm] = bv; c_nj[cl * 2 + wm] = bi; }
            }
        }
    }
    __syncthreads();

    if (tid < 128) {
        float v = r_nv[tid * 4]; int bj = r_nj[tid * 4];
        #pragma unroll
        for (int w = 1; w < 4; w++) {
            const float ov = r_nv[tid * 4 + w];
            const int   oj = r_nj[tid * 4 + w];
            if (ov < v || (ov == v && oj < bj)) { v = ov; bj = oj; }
        }
        g_cand_v[(size_t)(i0 + tid) * NTJ + tj] = v;
        g_cand_j[(size_t)(i0 + tid) * NTJ + tj] = bj;

        if (diag) {
            float pv = r_pv[tid * 4]; int pj = r_pj[tid * 4];
            #pragma unroll
            for (int w = 1; w < 4; w++) {
                const float ov = r_pv[tid * 4 + w];
                const int   oj = r_pj[tid * 4 + w];
                if (ov > pv || (ov == pv && oj < pj)) { pv = ov; pj = oj; }
            }
            g_pos_idx[i0 + tid] = pj;
        }
    } else if (!diag) {
        const int c = tid - 128;
        float v = c_nv[c * 2]; int bi = c_nj[c * 2];
        const float ov = c_nv[c * 2 + 1];
        const int   oi = c_nj[c * 2 + 1];
        if (ov < v || (ov == v && oi < bi)) { v = ov; bi = oi; }
        g_cand_v[(size_t)(j0 + c) * NTJ + ti] = v;
        g_cand_j[(size_t)(j0 + c) * NTJ + ti] = bi;
    }
}

// ---------------- fused finalize: candidates -> exact loss -> deterministic mean ----------------
#define LB 256
__global__ __launch_bounds__(256) void loss_kernel(const float* __restrict__ emb,
                                                   float* __restrict__ out) {
    const int wid = threadIdx.x >> 5, lane = threadIdx.x & 31;
    __shared__ float warp_sum[8];

    float lsum = 0.f;
    #pragma unroll 1
    for (int r = 0; r < NN / (LB * 8); r++) {            // 2 rows per warp
        const int i = blockIdx.x * (NN / LB) + wid * (NN / (LB * 8)) + r;

        float v = g_cand_v[(size_t)i * NTJ + lane];
        int  bj = g_cand_j[(size_t)i * NTJ + lane];
        #pragma unroll
        for (int off = 16; off; off >>= 1) {
            const float ov = __shfl_xor_sync(0xffffffffu, v,  off);
            const int   oi = __shfl_xor_sync(0xffffffffu, bj, off);
            if (ov < v || (ov == v && oi < bj)) { v = ov; bj = oi; }
        }
        const int n = bj;
        const int p = g_pos_idx[i];

        const float4* ei = (const float4*)(emb + (size_t)i * DD);
        const float4* ep = (const float4*)(emb + (size_t)p * DD);
        const float4* en = (const float4*)(emb + (size_t)n * DD);

        float sp = 0.f, sn = 0.f;
        #pragma unroll
        for (int t = 0; t < 2; t++) {
            const int q = lane + 32 * t;
            float4 a = __ldg(&ei[q]);
            float4 b = __ldg(&ep[q]);
            float4 d = __ldg(&en[q]);
            float x;
            x = a.x - b.x + EPSF; sp += x * x;
            x = a.y - b.y + EPSF; sp += x * x;
            x = a.z - b.z + EPSF; sp += x * x;
            x = a.w - b.w + EPSF; sp += x * x;
            x = a.x - d.x + EPSF; sn += x * x;
            x = a.y - d.y + EPSF; sn += x * x;
            x = a.z - d.z + EPSF; sn += x * x;
            x = a.w - d.w + EPSF; sn += x * x;
        }
        #pragma unroll
        for (int off = 16; off; off >>= 1) {
            sp += __shfl_xor_sync(0xffffffffu, sp, off);
            sn += __shfl_xor_sync(0xffffffffu, sn, off);
        }
        if (lane == 0)
            lsum += fmaxf(sqrtf(sp) - sqrtf(sn) + MARGINF, 0.f);
    }
    if (lane == 0) warp_sum[wid] = lsum;
    __syncthreads();

    if (threadIdx.x == 0) {
        double s = 0.0;
        #pragma unroll
        for (int w = 0; w < 8; w++) s += (double)warp_sum[w];
        const unsigned long long fx = (unsigned long long)(s * FIX_SCALE + 0.5);
        atomicAdd(&g_sum_fix, fx);
        __threadfence();
        const unsigned done = atomicAdd(&g_done, 1u);
        if (done == LB - 1) {
            const unsigned long long tot = atomicAdd(&g_sum_fix, 0ull);
            out[0] = (float)((double)tot / FIX_SCALE / (double)NN);
        }
    }
}

extern "C" void kernel_launch(void* const* d_in, const int* in_sizes, int n_in,
                              void* d_out, int out_size) {
    const float* emb = (const float*)d_in[0];
    float* out = (float*)d_out;

    static bool attr_set = false;
    if (!attr_set) {
        cudaFuncSetAttribute(gemm_kernel, cudaFuncAttributeMaxDynamicSharedMemorySize, DYN_SMEM);
        attr_set = true;
    }

    prep_kernel<<<NN / 8, 256>>>(emb);
    gemm_kernel<<<NTILES, 256, DYN_SMEM>>>();
    loss_kernel<<<LB, 256>>>(emb, out);
}

// round 9
// speedup vs baseline: 1.8533x; 1.4472x over previous
#include <cuda_runtime.h>
#include <cuda_bf16.h>
#include <cstdint>

#define NC 256
#define KK 16
#define DD 256
#define NN 4096
#define MARGINF 1.0f
#define EPSF 1e-6f

#define TI 128
#define TJ 128
#define KC 64            // bf16 per k-chunk (128B rows)
#define NCHUNK 4         // K = 256 (hi-only)
#define NTI (NN / TI)    // 32
#define NTILES (NTI * (NTI + 1) / 2)   // 528

#define STAGE_BYTES (TI*128 + TJ*128)   // 32 KB
#define SQ_OFF      (3 * STAGE_BYTES)   // 96 KB
#define DYN_SMEM    (SQ_OFF + 1024)

typedef unsigned long long u64;

__device__ __nv_bfloat16 g_panel[(size_t)NN * 256];   // hi only
__device__ float g_sq[NN];
__device__ u64   g_neg_pack[NN];    // (d2_bits<<32)|j      : atomicMin
__device__ u64   g_pos_pack[NN];    // (d2_bits<<32)|~j     : atomicMax
__device__ u64   g_sum_fix;
__device__ unsigned int g_done;

#define FIX_SCALE 17592186044416.0   // 2^44

#define LDSM4(r, a) \
    asm volatile("ldmatrix.sync.aligned.m8n8.x4.shared.b16 {%0,%1,%2,%3}, [%4];" \
        : "=r"((r)[0]), "=r"((r)[1]), "=r"((r)[2]), "=r"((r)[3]) : "r"(a))

#define MMA16816(c, a, b) \
    asm volatile("mma.sync.aligned.m16n8k16.row.col.f32.bf16.bf16.f32 " \
        "{%0,%1,%2,%3}, {%4,%5,%6,%7}, {%8,%9}, {%0,%1,%2,%3};" \
        : "+f"((c)[0]), "+f"((c)[1]), "+f"((c)[2]), "+f"((c)[3]) \
        : "r"((a)[0]), "r"((a)[1]), "r"((a)[2]), "r"((a)[3]), \
          "r"((b)[0]), "r"((b)[1]))

__device__ __forceinline__ void cp16(uint32_t dst, const void* src) {
    asm volatile("cp.async.cg.shared.global [%0], [%1], 16;" :: "r"(dst), "l"(src));
}
#define CP_COMMIT() asm volatile("cp.async.commit_group;")
#define CP_WAIT(n)  asm volatile("cp.async.wait_group %0;" :: "n"(n))

// ---------------- prep: fp32 -> bf16 hi panel + sq + init accumulators ----------------
__global__ __launch_bounds__(256) void prep_kernel(const float* __restrict__ emb) {
    if (blockIdx.x == 0 && threadIdx.x == 0) { g_sum_fix = 0ull; g_done = 0u; }

    const int row  = blockIdx.x * 8 + (threadIdx.x >> 5);
    const int lane = threadIdx.x & 31;

    const float4* src = (const float4*)(emb + (size_t)row * DD);
    float4 a = __ldg(&src[lane * 2]);
    float4 b = __ldg(&src[lane * 2 + 1]);
    float x[8] = {a.x, a.y, a.z, a.w, b.x, b.y, b.z, b.w};

    alignas(16) __nv_bfloat16 hi[8];
    float s = 0.f;
    #pragma unroll
    for (int t = 0; t < 8; t++) {
        hi[t] = __float2bfloat16(x[t]);
        s += x[t] * x[t];
    }
    *(uint4*)(g_panel + (size_t)row * 256 + lane * 8) = *(const uint4*)hi;

    #pragma unroll
    for (int off = 16; off; off >>= 1)
        s += __shfl_xor_sync(0xffffffffu, s, off);
    if (lane == 0) {
        g_sq[row] = s;
        g_neg_pack[row] = 0xffffffffffffffffull;
        g_pos_pack[row] = 0ull;
    }
}

__device__ __forceinline__ u64 pack_min(float v, int j) {
    return ((u64)__float_as_uint(fmaxf(v, 0.f)) << 32) | (unsigned)j;
}
__device__ __forceinline__ u64 pack_max(float v, int j) {
    return ((u64)__float_as_uint(fmaxf(v, 0.f)) << 32) | (unsigned)(~j);
}

// ---------------- triangular GEMM (HMMA, cp.async pipeline) + atomic epilogue ----------------
__global__ __launch_bounds__(256, 2)
void gemm_kernel() {
    extern __shared__ char dsm[];
    const int tid = threadIdx.x;

    // decode blockIdx.x -> (ti, tj) with tj >= ti
    int rem = blockIdx.x, ti = 0;
    while (rem >= NTI - ti) { rem -= NTI - ti; ti++; }
    const int tj = ti + rem;

    const int i0 = ti * TI;
    const int j0 = tj * TJ;
    const int wid = tid >> 5, lane = tid & 31;
    const int wm  = wid >> 2, wn = wid & 3;   // 2 x 4 warp grid
    const bool diag = (ti == tj);

    const uint32_t sbase = (uint32_t)__cvta_generic_to_shared(dsm);
    float* s_sqi = (float*)(dsm + SQ_OFF);
    float* s_sqj = (float*)(dsm + SQ_OFF + 512);

    const char* gp = (const char*)g_panel;

    auto load_stage = [&](int kc, int s) {
        const uint32_t aBase = sbase + s * STAGE_BYTES;
        const uint32_t bBase = aBase + TI * 128;
        const int koff = kc * KC;
        #pragma unroll
        for (int it = 0; it < 4; it++) {
            const int idx = tid + 256 * it;
            const int row = idx >> 3, seg = idx & 7;
            const int off = row * 128 + seg * 16;
            cp16(aBase + (off ^ ((off >> 3) & 0x70)),
                 gp + ((size_t)(i0 + row) * 256 + koff + seg * 8) * 2);
        }
        #pragma unroll
        for (int it = 0; it < 4; it++) {
            const int idx = tid + 256 * it;
            const int row = idx >> 3, seg = idx & 7;
            const int off = row * 128 + seg * 16;
            cp16(bBase + (off ^ ((off >> 3) & 0x70)),
                 gp + ((size_t)(j0 + row) * 256 + koff + seg * 8) * 2);
        }
        CP_COMMIT();
    };

    // fill pipeline first, then blocking sq gathers
    load_stage(0, 0);
    load_stage(1, 1);

    if (tid < 128) s_sqi[tid] = g_sq[i0 + tid];
    else           s_sqj[tid - 128] = g_sq[j0 + tid - 128];

    float acc[4][4][4];
    #pragma unroll
    for (int a = 0; a < 4; a++)
        #pragma unroll
        for (int b = 0; b < 4; b++)
            #pragma unroll
            for (int c = 0; c < 4; c++) acc[a][b][c] = 0.f;

    #pragma unroll 1
    for (int kc = 0; kc < NCHUNK; kc++) {
        if (kc < NCHUNK - 1) { CP_WAIT(1); }
        else                 { CP_WAIT(0); }
        __syncthreads();   // stage kc visible to all; all warps done with kc-1

        if (kc + 2 < NCHUNK) load_stage(kc + 2, (kc + 2) % 3);

        const uint32_t aBase = sbase + (kc % 3) * STAGE_BYTES;
        const uint32_t bBase = aBase + TI * 128;

        #pragma unroll
        for (int ks = 0; ks < 4; ks++) {
            uint32_t afr[4][4];
            #pragma unroll
            for (int fm = 0; fm < 4; fm++) {
                const int row = wm * 64 + fm * 16 + (lane & 15);
                const int ch  = (ks * 2 + (lane >> 4)) ^ (row & 7);
                LDSM4(afr[fm], aBase + row * 128 + ch * 16);
            }
            uint32_t bfr[2][4];
            #pragma unroll
            for (int g = 0; g < 2; g++) {
                const int row = wn * 32 + g * 16 + (lane & 7) + ((lane >> 4) & 1) * 8;
                const int ch  = (ks * 2 + ((lane >> 3) & 1)) ^ (row & 7);
                LDSM4(bfr[g], bBase + row * 128 + ch * 16);
            }
            #pragma unroll
            for (int fm = 0; fm < 4; fm++)
                #pragma unroll
                for (int fn = 0; fn < 4; fn++)
                    MMA16816(acc[fm][fn], afr[fm], &bfr[fn >> 1][(fn & 1) * 2]);
        }
    }

    // ---- epilogue: packed atomics, no smem reduce ----
    // row-side (all tiles): per-row first-min of d2 (+ first-max within cluster on diag)
    #pragma unroll
    for (int fm = 0; fm < 4; fm++) {
        #pragma unroll
        for (int h = 0; h < 2; h++) {
            const int rl = wm * 64 + fm * 16 + h * 8 + (lane >> 2);
            const int i  = i0 + rl;
            const int ci = i >> 4;
            const float sqi = s_sqi[rl];

            float bnv = 3.0e38f;  int bnj = 0x7fffffff;
            float bpv = -3.0e38f; int bpj = 0;

            #pragma unroll
            for (int fn = 0; fn < 4; fn++) {
                #pragma unroll
                for (int e = 0; e < 2; e++) {
                    const int cl = wn * 32 + fn * 8 + (lane & 3) * 2 + e;
                    const int j  = j0 + cl;
                    const float d2 = sqi + s_sqj[cl] - 2.f * acc[fm][fn][h * 2 + e];
                    if (diag && ((j >> 4) == ci)) {
                        if (d2 > bpv) { bpv = d2; bpj = j; }
                    } else {
                        if (d2 < bnv) { bnv = d2; bnj = j; }
                    }
                }
            }
            // quad reduce (lanes differing in bits 0-1)
            #pragma unroll
            for (int m = 1; m <= 2; m <<= 1) {
                float ov; int oj;
                ov = __shfl_xor_sync(0xffffffffu, bnv, m);
                oj = __shfl_xor_sync(0xffffffffu, bnj, m);
                if (ov < bnv || (ov == bnv && oj < bnj)) { bnv = ov; bnj = oj; }
                ov = __shfl_xor_sync(0xffffffffu, bpv, m);
                oj = __shfl_xor_sync(0xffffffffu, bpj, m);
                if (ov > bpv || (ov == bpv && oj < bpj)) { bpv = ov; bpj = oj; }
            }
            if ((lane & 3) == 0) {
                atomicMin(&g_neg_pack[i], pack_min(bnv, bnj));
                if (diag) atomicMax(&g_pos_pack[i], pack_max(bpv, bpj));
            }
        }
    }

    // col-side (off-diag only): per-column first-min, index = row i
    if (!diag) {
        #pragma unroll
        for (int fn = 0; fn < 4; fn++) {
            #pragma unroll
            for (int e = 0; e < 2; e++) {
                const int cl = wn * 32 + fn * 8 + (lane & 3) * 2 + e;
                const float sqj = s_sqj[cl];
                float bv = 3.0e38f; int bi = 0x7fffffff;
                #pragma unroll
                for (int fm = 0; fm < 4; fm++) {
                    #pragma unroll
                    for (int h = 0; h < 2; h++) {
                        const int rl = wm * 64 + fm * 16 + h * 8 + (lane >> 2);
                        const float d2 = s_sqi[rl] + sqj - 2.f * acc[fm][fn][h * 2 + e];
                        if (d2 < bv) { bv = d2; bi = i0 + rl; }
                    }
                }
                #pragma unroll
                for (int m = 4; m <= 16; m <<= 1) {
                    const float ov = __shfl_xor_sync(0xffffffffu, bv, m);
                    const int   oi = __shfl_xor_sync(0xffffffffu, bi, m);
                    if (ov < bv || (ov == bv && oi < bi)) { bv = ov; bi = oi; }
                }
                if ((lane >> 2) == 0)
                    atomicMin(&g_neg_pack[j0 + cl], pack_min(bv, bi));
            }
        }
    }
}

// ---------------- fused finalize: gather -> exact loss -> deterministic mean ----------------
#define LB 512
__global__ __launch_bounds__(256) void loss_kernel(const float* __restrict__ emb,
                                                   float* __restrict__ out) {
    const int wid = threadIdx.x >> 5, lane = threadIdx.x & 31;
    __shared__ float warp_sum[8];

    const int i = blockIdx.x * 8 + wid;

    const int n = (int)(unsigned)(g_neg_pack[i] & 0xffffffffull);
    const int p = (int)~(unsigned)(g_pos_pack[i] & 0xffffffffull);

    const float4* ei = (const float4*)(emb + (size_t)i * DD);
    const float4* ep = (const float4*)(emb + (size_t)p * DD);
    const float4* en = (const float4*)(emb + (size_t)n * DD);

    float sp = 0.f, sn = 0.f;
    #pragma unroll
    for (int t = 0; t < 2; t++) {
        const int q = lane + 32 * t;
        float4 a = __ldg(&ei[q]);
        float4 b = __ldg(&ep[q]);
        float4 d = __ldg(&en[q]);
        float x;
        x = a.x - b.x + EPSF; sp += x * x;
        x = a.y - b.y + EPSF; sp += x * x;
        x = a.z - b.z + EPSF; sp += x * x;
        x = a.w - b.w + EPSF; sp += x * x;
        x = a.x - d.x + EPSF; sn += x * x;
        x = a.y - d.y + EPSF; sn += x * x;
        x = a.z - d.z + EPSF; sn += x * x;
        x = a.w - d.w + EPSF; sn += x * x;
    }
    #pragma unroll
    for (int off = 16; off; off >>= 1) {
        sp += __shfl_xor_sync(0xffffffffu, sp, off);
        sn += __shfl_xor_sync(0xffffffffu, sn, off);
    }
    if (lane == 0)
        warp_sum[wid] = fmaxf(sqrtf(sp) - sqrtf(sn) + MARGINF, 0.f);
    __syncthreads();

    if (threadIdx.x == 0) {
        double s = 0.0;
        #pragma unroll
        for (int w = 0; w < 8; w++) s += (double)warp_sum[w];
        const u64 fx = (u64)(s * FIX_SCALE + 0.5);
        atomicAdd(&g_sum_fix, fx);
        __threadfence();
        const unsigned done = atomicAdd(&g_done, 1u);
        if (done == LB - 1) {
            const u64 tot = atomicAdd(&g_sum_fix, 0ull);
            out[0] = (float)((double)tot / FIX_SCALE / (double)NN);
        }
    }
}

extern "C" void kernel_launch(void* const* d_in, const int* in_sizes, int n_in,
                              void* d_out, int out_size) {
    const float* emb = (const float*)d_in[0];
    float* out = (float*)d_out;

    static bool attr_set = false;
    if (!attr_set) {
        cudaFuncSetAttribute(gemm_kernel, cudaFuncAttributeMaxDynamicSharedMemorySize, DYN_SMEM);
        attr_set = true;
    }

    prep_kernel<<<NN / 8, 256>>>(emb);
    gemm_kernel<<<NTILES, 256, DYN_SMEM>>>();
    loss_kernel<<<LB, 256>>>(emb, out);
}

// round 10
// speedup vs baseline: 1.9641x; 1.0598x over previous
#include <cuda_runtime.h>
#include <cuda_bf16.h>
#include <cstdint>

#define NC 256
#define KK 16
#define DD 256
#define NN 4096
#define MARGINF 1.0f
#define EPSF 1e-6f

#define TI 128
#define TJ 128
#define KC 64            // bf16 per k-chunk (128B rows)
#define NCHUNK 4         // K = 256 (hi-only)
#define NTI (NN / TI)    // 32
#define NTILES (NTI * (NTI + 1) / 2)   // 528

#define STAGE_BYTES (TI*128 + TJ*128)   // 32 KB
#define SQ_OFF      (3 * STAGE_BYTES)   // 96 KB
#define DYN_SMEM    (SQ_OFF + 1024)

typedef unsigned long long u64;

__device__ __nv_bfloat16 g_panel[(size_t)NN * 256];   // hi only
__device__ float g_sq[NN];
__device__ float g_sum[NN];         // row sums (for eps correction)
__device__ u64   g_neg_pack[NN];    // (d2_bits<<32)|j      : atomicMin
__device__ u64   g_pos_pack[NN];    // (d2_bits<<32)|~j     : atomicMax
__device__ u64   g_sum_fix;
__device__ unsigned int g_done;

#define FIX_SCALE 17592186044416.0   // 2^44

#define LDSM4(r, a) \
    asm volatile("ldmatrix.sync.aligned.m8n8.x4.shared.b16 {%0,%1,%2,%3}, [%4];" \
        : "=r"((r)[0]), "=r"((r)[1]), "=r"((r)[2]), "=r"((r)[3]) : "r"(a))

#define MMA16816(c, a, b) \
    asm volatile("mma.sync.aligned.m16n8k16.row.col.f32.bf16.bf16.f32 " \
        "{%0,%1,%2,%3}, {%4,%5,%6,%7}, {%8,%9}, {%0,%1,%2,%3};" \
        : "+f"((c)[0]), "+f"((c)[1]), "+f"((c)[2]), "+f"((c)[3]) \
        : "r"((a)[0]), "r"((a)[1]), "r"((a)[2]), "r"((a)[3]), \
          "r"((b)[0]), "r"((b)[1]))

__device__ __forceinline__ void cp16(uint32_t dst, const void* src) {
    asm volatile("cp.async.cg.shared.global [%0], [%1], 16;" :: "r"(dst), "l"(src));
}
#define CP_COMMIT() asm volatile("cp.async.commit_group;")
#define CP_WAIT(n)  asm volatile("cp.async.wait_group %0;" :: "n"(n))

// ---------------- prep: fp32 -> bf16 hi panel + sq + sum + init accumulators ----------------
__global__ __launch_bounds__(256) void prep_kernel(const float* __restrict__ emb) {
    if (blockIdx.x == 0 && threadIdx.x == 0) { g_sum_fix = 0ull; g_done = 0u; }

    const int row  = blockIdx.x * 8 + (threadIdx.x >> 5);
    const int lane = threadIdx.x & 31;

    const float4* src = (const float4*)(emb + (size_t)row * DD);
    float4 a = __ldg(&src[lane * 2]);
    float4 b = __ldg(&src[lane * 2 + 1]);
    float x[8] = {a.x, a.y, a.z, a.w, b.x, b.y, b.z, b.w};

    alignas(16) __nv_bfloat16 hi[8];
    float s = 0.f, m = 0.f;
    #pragma unroll
    for (int t = 0; t < 8; t++) {
        hi[t] = __float2bfloat16(x[t]);
        s += x[t] * x[t];
        m += x[t];
    }
    *(uint4*)(g_panel + (size_t)row * 256 + lane * 8) = *(const uint4*)hi;

    #pragma unroll
    for (int off = 16; off; off >>= 1) {
        s += __shfl_xor_sync(0xffffffffu, s, off);
        m += __shfl_xor_sync(0xffffffffu, m, off);
    }
    if (lane == 0) {
        g_sq[row]  = s;
        g_sum[row] = m;
        g_neg_pack[row] = 0xffffffffffffffffull;
        g_pos_pack[row] = 0ull;
    }
}

__device__ __forceinline__ u64 pack_min(float v, int j) {
    return ((u64)__float_as_uint(fmaxf(v, 0.f)) << 32) | (unsigned)j;
}
__device__ __forceinline__ u64 pack_max(float v, int j) {
    return ((u64)__float_as_uint(fmaxf(v, 0.f)) << 32) | (unsigned)(~j);
}

// ---------------- triangular GEMM (HMMA, cp.async pipeline) + atomic epilogue ----------------
__global__ __launch_bounds__(256, 2)
void gemm_kernel() {
    extern __shared__ char dsm[];
    const int tid = threadIdx.x;

    // decode blockIdx.x -> (ti, tj) with tj >= ti
    int rem = blockIdx.x, ti = 0;
    while (rem >= NTI - ti) { rem -= NTI - ti; ti++; }
    const int tj = ti + rem;

    const int i0 = ti * TI;
    const int j0 = tj * TJ;
    const int wid = tid >> 5, lane = tid & 31;
    const int wm  = wid >> 2, wn = wid & 3;   // 2 x 4 warp grid
    const bool diag = (ti == tj);

    const uint32_t sbase = (uint32_t)__cvta_generic_to_shared(dsm);
    float* s_sqi = (float*)(dsm + SQ_OFF);
    float* s_sqj = (float*)(dsm + SQ_OFF + 512);

    const char* gp = (const char*)g_panel;

    auto load_stage = [&](int kc, int s) {
        const uint32_t aBase = sbase + s * STAGE_BYTES;
        const uint32_t bBase = aBase + TI * 128;
        const int koff = kc * KC;
        #pragma unroll
        for (int it = 0; it < 4; it++) {
            const int idx = tid + 256 * it;
            const int row = idx >> 3, seg = idx & 7;
            const int off = row * 128 + seg * 16;
            cp16(aBase + (off ^ ((off >> 3) & 0x70)),
                 gp + ((size_t)(i0 + row) * 256 + koff + seg * 8) * 2);
        }
        #pragma unroll
        for (int it = 0; it < 4; it++) {
            const int idx = tid + 256 * it;
            const int row = idx >> 3, seg = idx & 7;
            const int off = row * 128 + seg * 16;
            cp16(bBase + (off ^ ((off >> 3) & 0x70)),
                 gp + ((size_t)(j0 + row) * 256 + koff + seg * 8) * 2);
        }
        CP_COMMIT();
    };

    // fill pipeline first, then blocking sq gathers
    load_stage(0, 0);
    load_stage(1, 1);

    if (tid < 128) s_sqi[tid] = g_sq[i0 + tid];
    else           s_sqj[tid - 128] = g_sq[j0 + tid - 128];

    float acc[4][4][4];
    #pragma unroll
    for (int a = 0; a < 4; a++)
        #pragma unroll
        for (int b = 0; b < 4; b++)
            #pragma unroll
            for (int c = 0; c < 4; c++) acc[a][b][c] = 0.f;

    #pragma unroll 1
    for (int kc = 0; kc < NCHUNK; kc++) {
        if (kc < NCHUNK - 1) { CP_WAIT(1); }
        else                 { CP_WAIT(0); }
        __syncthreads();   // stage kc visible to all; all warps done with kc-1

        if (kc + 2 < NCHUNK) load_stage(kc + 2, (kc + 2) % 3);

        const uint32_t aBase = sbase + (kc % 3) * STAGE_BYTES;
        const uint32_t bBase = aBase + TI * 128;

        #pragma unroll
        for (int ks = 0; ks < 4; ks++) {
            uint32_t afr[4][4];
            #pragma unroll
            for (int fm = 0; fm < 4; fm++) {
                const int row = wm * 64 + fm * 16 + (lane & 15);
                const int ch  = (ks * 2 + (lane >> 4)) ^ (row & 7);
                LDSM4(afr[fm], aBase + row * 128 + ch * 16);
            }
            uint32_t bfr[2][4];
            #pragma unroll
            for (int g = 0; g < 2; g++) {
                const int row = wn * 32 + g * 16 + (lane & 7) + ((lane >> 4) & 1) * 8;
                const int ch  = (ks * 2 + ((lane >> 3) & 1)) ^ (row & 7);
                LDSM4(bfr[g], bBase + row * 128 + ch * 16);
            }
            #pragma unroll
            for (int fm = 0; fm < 4; fm++)
                #pragma unroll
                for (int fn = 0; fn < 4; fn++)
                    MMA16816(acc[fm][fn], afr[fm], &bfr[fn >> 1][(fn & 1) * 2]);
        }
    }

    // ---- epilogue: packed atomics ----
    #pragma unroll
    for (int fm = 0; fm < 4; fm++) {
        #pragma unroll
        for (int h = 0; h < 2; h++) {
            const int rl = wm * 64 + fm * 16 + h * 8 + (lane >> 2);
            const int i  = i0 + rl;
            const int ci = i >> 4;
            const float sqi = s_sqi[rl];

            float bnv = 3.0e38f;  int bnj = 0x7fffffff;
            float bpv = -3.0e38f; int bpj = 0;

            #pragma unroll
            for (int fn = 0; fn < 4; fn++) {
                #pragma unroll
                for (int e = 0; e < 2; e++) {
                    const int cl = wn * 32 + fn * 8 + (lane & 3) * 2 + e;
                    const int j  = j0 + cl;
                    const float d2 = sqi + s_sqj[cl] - 2.f * acc[fm][fn][h * 2 + e];
                    if (diag && ((j >> 4) == ci)) {
                        if (d2 > bpv) { bpv = d2; bpj = j; }
                    } else {
                        if (d2 < bnv) { bnv = d2; bnj = j; }
                    }
                }
            }
            #pragma unroll
            for (int m = 1; m <= 2; m <<= 1) {
                float ov; int oj;
                ov = __shfl_xor_sync(0xffffffffu, bnv, m);
                oj = __shfl_xor_sync(0xffffffffu, bnj, m);
                if (ov < bnv || (ov == bnv && oj < bnj)) { bnv = ov; bnj = oj; }
                ov = __shfl_xor_sync(0xffffffffu, bpv, m);
                oj = __shfl_xor_sync(0xffffffffu, bpj, m);
                if (ov > bpv || (ov == bpv && oj < bpj)) { bpv = ov; bpj = oj; }
            }
            if ((lane & 3) == 0) {
                atomicMin(&g_neg_pack[i], pack_min(bnv, bnj));
                if (diag) atomicMax(&g_pos_pack[i], pack_max(bpv, bpj));
            }
        }
    }

    if (!diag) {
        #pragma unroll
        for (int fn = 0; fn < 4; fn++) {
            #pragma unroll
            for (int e = 0; e < 2; e++) {
                const int cl = wn * 32 + fn * 8 + (lane & 3) * 2 + e;
                const float sqj = s_sqj[cl];
                float bv = 3.0e38f; int bi = 0x7fffffff;
                #pragma unroll
                for (int fm = 0; fm < 4; fm++) {
                    #pragma unroll
                    for (int h = 0; h < 2; h++) {
                        const int rl = wm * 64 + fm * 16 + h * 8 + (lane >> 2);
                        const float d2 = s_sqi[rl] + sqj - 2.f * acc[fm][fn][h * 2 + e];
                        if (d2 < bv) { bv = d2; bi = i0 + rl; }
                    }
                }
                #pragma unroll
                for (int m = 4; m <= 16; m <<= 1) {
                    const float ov = __shfl_xor_sync(0xffffffffu, bv, m);
                    const int   oi = __shfl_xor_sync(0xffffffffu, bi, m);
                    if (ov < bv || (ov == bv && oi < bi)) { bv = ov; bi = oi; }
                }
                if ((lane >> 2) == 0)
                    atomicMin(&g_neg_pack[j0 + cl], pack_min(bv, bi));
            }
        }
    }
}

// ---------------- finalize: algebraic loss from packs (no embedding gathers) ----------------
#define LB 16
__global__ __launch_bounds__(256) void loss_kernel(float* __restrict__ out) {
    const int i = blockIdx.x * 256 + threadIdx.x;
    __shared__ float sh[256];

    const u64 np = g_neg_pack[i];
    const u64 pp = g_pos_pack[i];
    const int n = (int)(unsigned)(np & 0xffffffffull);
    const int p = (int)~(unsigned)(pp & 0xffffffffull);
    const float d2n = __uint_as_float((unsigned)(np >> 32));
    const float d2p = __uint_as_float((unsigned)(pp >> 32));

    const float Si = g_sum[i];
    const float eterm = (float)DD * EPSF * EPSF;

    const float ap2 = d2p + 2.f * EPSF * (Si - g_sum[p]) + eterm;
    const float an2 = d2n + 2.f * EPSF * (Si - g_sum[n]) + eterm;
    const float d_ap = sqrtf(fmaxf(ap2, 0.f));
    const float d_an = sqrtf(fmaxf(an2, 0.f));

    sh[threadIdx.x] = fmaxf(d_ap - d_an + MARGINF, 0.f);
    __syncthreads();

    for (int off = 128; off; off >>= 1) {
        if (threadIdx.x < off) sh[threadIdx.x] += sh[threadIdx.x + off];
        __syncthreads();
    }

    if (threadIdx.x == 0) {
        const u64 fx = (u64)((double)sh[0] * FIX_SCALE + 0.5);
        atomicAdd(&g_sum_fix, fx);
        __threadfence();
        const unsigned done = atomicAdd(&g_done, 1u);
        if (done == LB - 1) {
            const u64 tot = atomicAdd(&g_sum_fix, 0ull);
            out[0] = (float)((double)tot / FIX_SCALE / (double)NN);
        }
    }
}

extern "C" void kernel_launch(void* const* d_in, const int* in_sizes, int n_in,
                              void* d_out, int out_size) {
    const float* emb = (const float*)d_in[0];
    float* out = (float*)d_out;

    static bool attr_set = false;
    if (!attr_set) {
        cudaFuncSetAttribute(gemm_kernel, cudaFuncAttributeMaxDynamicSharedMemorySize, DYN_SMEM);
        attr_set = true;
    }

    prep_kernel<<<NN / 8, 256>>>(emb);
    gemm_kernel<<<NTILES, 256, DYN_SMEM>>>();
    loss_kernel<<<LB, 256>>>(out);
}